// round 9
// baseline (speedup 1.0000x reference)
#include <cuda_runtime.h>

typedef unsigned long long ull;

// ---------------------------------------------------------------------------
// Problem constants
// ---------------------------------------------------------------------------
namespace {
constexpr int Bn  = 2048;
constexpr int Sn  = 200;
constexpr int Tn  = 50;
constexpr int INn = 44;
constexpr int Hn  = 128;
constexpr int Ln  = 4;
constexpr long BH = (long)Bn * Hn;            // 262144 elems per (B,H) slab

// packed weights: per matrix 8 jb-tiles * K rows * 128 floats
constexpr long PK_IH0 = 8L * 44  * 128;       // 45056
constexpr long PK_128 = 8L * 128 * 128;       // 131072
constexpr long OFF_EIH0 = 0;
constexpr long OFF_EIHR = OFF_EIH0 + PK_IH0;
constexpr long OFF_EHH  = OFF_EIHR + 3 * PK_128;
constexpr long OFF_DIH0 = OFF_EHH  + 4 * PK_128;
constexpr long OFF_DIHR = OFF_DIH0 + PK_IH0;
constexpr long OFF_DHH  = OFF_DIHR + 3 * PK_128;
constexpr long PK_TOTAL = OFF_DHH  + 4 * PK_128;

constexpr int PITCH = 132;                    // sA pitch in floats (16B-aligned rows)
}

// ---------------------------------------------------------------------------
// Scratch (static device globals; no runtime allocation allowed)
// ---------------------------------------------------------------------------
__device__ float g_ysA[(long)Sn * Bn * Hn];       // 209.7 MB
__device__ float g_ysB[(long)Sn * Bn * Hn];       // 209.7 MB
__device__ float g_encC[(long)Ln * Bn * Hn];      // final cell state per enc layer
__device__ float g_decH[2L * Ln * Bn * Hn];       // decoder h ping-pong [2][L][B][H]
__device__ float g_out2[2L * Bn * INn];           // decoder output ping-pong
__device__ float g_wpk[PK_TOTAL];
__device__ unsigned g_barc[16];                   // per-mt barrier counters (zero-init)
__device__ unsigned g_bars[16];                   // per-mt barrier sense

// ---------------------------------------------------------------------------
// f32x2 helpers (sm_103a packed fp32 FMA)
// ---------------------------------------------------------------------------
__device__ __forceinline__ ull pk2(float x, float y) {
    ull r; asm("mov.b64 %0, {%1, %2};" : "=l"(r) : "f"(x), "f"(y)); return r;
}
__device__ __forceinline__ float2 upk(ull v) {
    float2 r; asm("mov.b64 {%0, %1}, %2;" : "=f"(r.x), "=f"(r.y) : "l"(v)); return r;
}
__device__ __forceinline__ void fmax2(ull& d, ull a, ull b) {
    asm("fma.rn.f32x2 %0, %1, %2, %0;" : "+l"(d) : "l"(a), "l"(b));
}
__device__ __forceinline__ float sigf(float x) {
    return __fdividef(1.f, 1.f + __expf(-x));
}
__device__ __forceinline__ float tanh_f(float x) {
    float xc = fminf(fmaxf(x, -15.f), 15.f);
    float e = __expf(2.f * xc);
    return __fdividef(e - 1.f, e + 1.f);
}

// ---------------------------------------------------------------------------
// mt-local barrier among the 8 CTAs sharing a batch-row tile (sense-reversing)
// ---------------------------------------------------------------------------
__device__ __forceinline__ void mt_barrier(int mt, unsigned* s_sense) {
    __threadfence();
    __syncthreads();
    if (threadIdx.x == 0) {
        unsigned ns = *s_sense ^ 1u;
        *s_sense = ns;
        unsigned a = atomicAdd(&g_barc[mt], 1u);
        if (a == 7u) {
            g_barc[mt] = 0u;
            __threadfence();
            atomicExch(&g_bars[mt], ns);
        } else {
            volatile unsigned* p = &g_bars[mt];
            while (*p != ns) __nanosleep(64);
            __threadfence();
        }
    }
    __syncthreads();
}

// ---------------------------------------------------------------------------
// Weight pre-pack:
// W (512 x K row-major, rows = gate*128 + j) ->
// Wpk[(jb*K + k)*128 + hu*8 + g*2 + dup]   (dup 0/1 identical; g in {i,f,g,o})
// so one LDS.128 at hu*8 yields (i,i,f,f); next yields (g,g,o,o).
// ---------------------------------------------------------------------------
__global__ void pack_w_kernel(const float* __restrict__ W, float* __restrict__ Wpk, int K) {
    int idx = blockIdx.x * blockDim.x + threadIdx.x;
    int total = 8 * K * 128;
    if (idx >= total) return;
    int inner = idx & 127;
    int rem   = idx >> 7;              // jb*K + k
    int k  = rem % K;
    int jb = rem / K;
    int hu = inner >> 3;
    int ge = (inner >> 1) & 3;
    Wpk[idx] = W[(long)(ge * 128 + jb * 16 + hu) * K + k];
}

// ---------------------------------------------------------------------------
// Persistent encoder layer kernel.
// grid = 128 CTAs: mt = bx>>3 (16 tiles of 128 batch rows), jb = bx&7 (16 units).
// 256 threads: hu = tid&15, mg = tid>>4 (16 groups of 8 rows).
// Weights (K1p+128 rows x 128 floats) resident in dynamic smem.
// c kept in registers for all S steps; h via global + mt-barrier.
// ---------------------------------------------------------------------------
__global__ __launch_bounds__(256, 1) void enc_layer_kernel(
    const float* __restrict__ A1, long lda1, long stepA1, int K1, int K1p,
    const float* __restrict__ Wpk1, const float* __restrict__ Wpk2,
    const float* __restrict__ bias,
    float* __restrict__ ysOut, float* __restrict__ hFinal, float* __restrict__ cFinal)
{
    extern __shared__ float sm[];
    const int Ktp = K1p + 128;
    float* sW  = sm;                       // Ktp*128 floats
    float* sA0 = sm + (long)Ktp * 128;     // 16*PITCH
    float* sA1 = sA0 + 16 * PITCH;
    __shared__ unsigned s_sense;

    int tid = threadIdx.x;
    int bx  = blockIdx.x;
    int mt = bx >> 3, jb = bx & 7;
    int m0 = mt * 128;
    int hu = tid & 15, mg = tid >> 4;
    int mg8 = mg * 8;
    int j = jb * 16 + hu;

    if (tid == 0) s_sense = *(volatile unsigned*)&g_bars[mt];

    // ---- load resident weights (once) ----
    {
        const float4* w1 = (const float4*)(Wpk1 + (long)jb * K1 * 128);
        int n1 = K1p * 32;                 // float4 count incl. zero pad rows
        for (int i = tid; i < n1; i += 256) {
            float4 v = make_float4(0.f, 0.f, 0.f, 0.f);
            if ((i >> 5) < K1) v = w1[i];
            ((float4*)sW)[i] = v;
        }
        const float4* w2 = (const float4*)(Wpk2 + (long)jb * 128 * 128);
        float4* d2 = (float4*)(sW + (long)K1p * 128);
        for (int i = tid; i < 128 * 32; i += 256) d2[i] = w2[i];
    }
    __syncthreads();

    float bi = bias[j], bf = bias[128 + j], bg = bias[256 + j], bo = bias[384 + j];
    float creg[8];
    #pragma unroll
    for (int i = 0; i < 8; i++) creg[i] = 0.f;

    const int nch = Ktp >> 4;

    for (int t = 0; t < Sn; t++) {
        ull accI[4], accF[4], accG[4], accO[4];
        #pragma unroll
        for (int p = 0; p < 4; p++) {
            accI[p] = pk2(bi, bi); accF[p] = pk2(bf, bf);
            accG[p] = pk2(bg, bg); accO[p] = pk2(bo, bo);
        }
        const float* hprev = ysOut + (long)(t - 1) * BH;   // valid iff t>0
        long aoff = (long)t * stepA1;

        float4 pf0, pf1;
        auto issue = [&](int kc) {
            #pragma unroll
            for (int it = 0; it < 2; it++) {
                int idx = tid + it * 256;
                int row = idx >> 2, q = idx & 3;
                int k = kc + q * 4;
                float4 v = make_float4(0.f, 0.f, 0.f, 0.f);
                if (kc < K1p) {
                    if (k + 4 <= K1) {
                        v = *(const float4*)(A1 + (long)(m0 + row) * lda1 + aoff + k);
                    } else if (k < K1) {
                        const float* s = A1 + (long)(m0 + row) * lda1 + aoff + k;
                        v.x = s[0];
                        if (k + 1 < K1) v.y = s[1];
                        if (k + 2 < K1) v.z = s[2];
                    }
                } else if (t > 0) {
                    v = *(const float4*)(hprev + (long)(m0 + row) * Hn + (k - K1p));
                }
                if (it) pf1 = v; else pf0 = v;
            }
        };
        auto commit = [&](float* buf) {
            #pragma unroll
            for (int it = 0; it < 2; it++) {
                int idx = tid + it * 256;
                int row = idx >> 2, q = idx & 3;
                float4 v = it ? pf1 : pf0;
                float* d = buf + (q * 4) * PITCH + row;
                d[0] = v.x; d[PITCH] = v.y; d[2 * PITCH] = v.z; d[3 * PITCH] = v.w;
            }
        };

        issue(0);
        commit(sA0);
        __syncthreads();
        for (int c = 0; c < nch; c++) {
            float* cur = (c & 1) ? sA1 : sA0;
            float* nxt = (c & 1) ? sA0 : sA1;
            bool more = (c + 1) < nch;
            if (more) issue((c + 1) << 4);
            const float* swb = sW + (long)(c << 4) * 128 + hu * 8;
            const float* sab = cur + mg8;
            #pragma unroll
            for (int kk = 0; kk < 16; kk++) {
                ulonglong2 wa  = *(const ulonglong2*)(swb + kk * 128);       // (i,i),(f,f)
                ulonglong2 wb2 = *(const ulonglong2*)(swb + kk * 128 + 4);   // (g,g),(o,o)
                ulonglong2 a01 = *(const ulonglong2*)(sab + kk * PITCH);
                ulonglong2 a23 = *(const ulonglong2*)(sab + kk * PITCH + 4);
                fmax2(accI[0], a01.x, wa.x);  fmax2(accI[1], a01.y, wa.x);
                fmax2(accI[2], a23.x, wa.x);  fmax2(accI[3], a23.y, wa.x);
                fmax2(accF[0], a01.x, wa.y);  fmax2(accF[1], a01.y, wa.y);
                fmax2(accF[2], a23.x, wa.y);  fmax2(accF[3], a23.y, wa.y);
                fmax2(accG[0], a01.x, wb2.x); fmax2(accG[1], a01.y, wb2.x);
                fmax2(accG[2], a23.x, wb2.x); fmax2(accG[3], a23.y, wb2.x);
                fmax2(accO[0], a01.x, wb2.y); fmax2(accO[1], a01.y, wb2.y);
                fmax2(accO[2], a23.x, wb2.y); fmax2(accO[3], a23.y, wb2.y);
            }
            if (more) commit(nxt);
            __syncthreads();
        }

        // ---- LSTM cell epilogue ----
        float* hout = ysOut + (long)t * BH;
        bool last = (t == Sn - 1);
        #pragma unroll
        for (int p = 0; p < 4; p++) {
            float2 vi = upk(accI[p]), vf = upk(accF[p]);
            float2 vg = upk(accG[p]), vo = upk(accO[p]);
            #pragma unroll
            for (int h2 = 0; h2 < 2; h2++) {
                int r = m0 + mg8 + 2 * p + h2;
                float gi = h2 ? vi.y : vi.x;
                float gf = h2 ? vf.y : vf.x;
                float gg = h2 ? vg.y : vg.x;
                float go = h2 ? vo.y : vo.x;
                float cc = creg[2 * p + h2];
                float cn = sigf(gf) * cc + sigf(gi) * tanh_f(gg);
                float hh = sigf(go) * tanh_f(cn);
                creg[2 * p + h2] = cn;
                long gi2 = (long)r * Hn + j;
                hout[gi2] = hh;
                if (last) { hFinal[gi2] = hh; cFinal[gi2] = cn; }
            }
        }
        mt_barrier(mt, &s_sense);
    }
}

// ---------------------------------------------------------------------------
// Persistent decoder kernel: T steps x 4 layers (weights streamed from L2)
// + fused FC. c for all 4 layers in registers.
// ---------------------------------------------------------------------------
__global__ __launch_bounds__(256, 1) void dec_kernel(
    const float* __restrict__ x,
    const float* __restrict__ wpk,
    const float* __restrict__ dec_b,
    const float* __restrict__ encC,
    float* __restrict__ decH,             // [2][L][B][H]
    float* __restrict__ outbuf,           // [2][B][IN]
    const float* __restrict__ fcW, const float* __restrict__ fcb,
    float* __restrict__ dout)             // [B][T][IN]
{
    __shared__ __align__(16) float sW[2][16 * 128];
    __shared__ __align__(16) float sA[2][16 * PITCH];
    __shared__ unsigned s_sense;

    int tid = threadIdx.x;
    int bx  = blockIdx.x;
    int mt = bx >> 3, jb = bx & 7;
    int m0 = mt * 128;
    int hu = tid & 15, mg = tid >> 4;
    int mg8 = mg * 8;
    int j = jb * 16 + hu;

    if (tid == 0) s_sense = *(volatile unsigned*)&g_bars[mt];
    __syncthreads();

    // load initial c (encoder final) into registers
    float creg[Ln][8];
    #pragma unroll
    for (int l = 0; l < Ln; l++)
        #pragma unroll
        for (int e = 0; e < 8; e++)
            creg[l][e] = encC[(long)l * BH + (long)(m0 + mg8 + e) * Hn + j];

    for (int t = 0; t < Tn; t++) {
        int cur = t & 1, prv = cur ^ 1;
        for (int l = 0; l < Ln; l++) {
            int K1  = l ? 128 : INn;
            int K1p = l ? 128 : 48;
            int Ktp = K1p + 128;
            int nch = Ktp >> 4;
            const float* W1 = (l == 0)
                ? (wpk + OFF_DIH0 + (long)jb * INn * 128)
                : (wpk + OFF_DIHR + (long)(l - 1) * PK_128 + (long)jb * 128 * 128);
            const float* W2 = wpk + OFF_DHH + (long)l * PK_128 + (long)jb * 128 * 128;
            const float* A1; long lda1, aoff;
            if (l == 0) {
                if (t == 0) { A1 = x; lda1 = (long)Sn * INn; aoff = (long)(Sn - 1) * INn; }
                else        { A1 = outbuf + (long)prv * Bn * INn; lda1 = INn; aoff = 0; }
            } else {
                A1 = decH + ((long)cur * Ln + (l - 1)) * BH; lda1 = Hn; aoff = 0;
            }
            const float* hprev = decH + ((long)prv * Ln + l) * BH;
            const float* bias = dec_b + l * 512;

            float bi = bias[j], bf = bias[128 + j], bg = bias[256 + j], bo = bias[384 + j];
            ull accI[4], accF[4], accG[4], accO[4];
            #pragma unroll
            for (int p = 0; p < 4; p++) {
                accI[p] = pk2(bi, bi); accF[p] = pk2(bf, bf);
                accG[p] = pk2(bg, bg); accO[p] = pk2(bo, bo);
            }

            float4 pa0, pa1, pw0, pw1;
            auto issue = [&](int kc) {
                #pragma unroll
                for (int it = 0; it < 2; it++) {   // A
                    int idx = tid + it * 256;
                    int row = idx >> 2, q = idx & 3;
                    int k = kc + q * 4;
                    float4 v = make_float4(0.f, 0.f, 0.f, 0.f);
                    if (kc < K1p) {
                        if (k + 4 <= K1) {
                            v = *(const float4*)(A1 + (long)(m0 + row) * lda1 + aoff + k);
                        } else if (k < K1) {
                            const float* s = A1 + (long)(m0 + row) * lda1 + aoff + k;
                            v.x = s[0];
                            if (k + 1 < K1) v.y = s[1];
                            if (k + 2 < K1) v.z = s[2];
                        }
                    } else {
                        v = *(const float4*)(hprev + (long)(m0 + row) * Hn + (k - K1p));
                    }
                    if (it) pa1 = v; else pa0 = v;
                }
                #pragma unroll
                for (int it = 0; it < 2; it++) {   // W
                    int idx = tid + it * 256;
                    int kk = idx >> 5, c4 = idx & 31;
                    int k = kc + kk;
                    float4 v = make_float4(0.f, 0.f, 0.f, 0.f);
                    if (k < K1)       v = *(const float4*)(W1 + (long)k * 128 + c4 * 4);
                    else if (k >= K1p) v = *(const float4*)(W2 + (long)(k - K1p) * 128 + c4 * 4);
                    if (it) pw1 = v; else pw0 = v;
                }
            };
            auto commit = [&](int b) {
                #pragma unroll
                for (int it = 0; it < 2; it++) {
                    int idx = tid + it * 256;
                    int row = idx >> 2, q = idx & 3;
                    float4 v = it ? pa1 : pa0;
                    float* d = sA[b] + (q * 4) * PITCH + row;
                    d[0] = v.x; d[PITCH] = v.y; d[2 * PITCH] = v.z; d[3 * PITCH] = v.w;
                }
                #pragma unroll
                for (int it = 0; it < 2; it++) {
                    int idx = tid + it * 256;
                    int kk = idx >> 5, c4 = idx & 31;
                    *(float4*)(sW[b] + kk * 128 + c4 * 4) = it ? pw1 : pw0;
                }
            };

            issue(0);
            commit(0);
            __syncthreads();
            for (int c = 0; c < nch; c++) {
                int cb = c & 1;
                bool more = (c + 1) < nch;
                if (more) issue((c + 1) << 4);
                const float* swb = sW[cb] + hu * 8;
                const float* sab = sA[cb] + mg8;
                #pragma unroll
                for (int kk = 0; kk < 16; kk++) {
                    ulonglong2 wa  = *(const ulonglong2*)(swb + kk * 128);
                    ulonglong2 wb2 = *(const ulonglong2*)(swb + kk * 128 + 4);
                    ulonglong2 a01 = *(const ulonglong2*)(sab + kk * PITCH);
                    ulonglong2 a23 = *(const ulonglong2*)(sab + kk * PITCH + 4);
                    fmax2(accI[0], a01.x, wa.x);  fmax2(accI[1], a01.y, wa.x);
                    fmax2(accI[2], a23.x, wa.x);  fmax2(accI[3], a23.y, wa.x);
                    fmax2(accF[0], a01.x, wa.y);  fmax2(accF[1], a01.y, wa.y);
                    fmax2(accF[2], a23.x, wa.y);  fmax2(accF[3], a23.y, wa.y);
                    fmax2(accG[0], a01.x, wb2.x); fmax2(accG[1], a01.y, wb2.x);
                    fmax2(accG[2], a23.x, wb2.x); fmax2(accG[3], a23.y, wb2.x);
                    fmax2(accO[0], a01.x, wb2.y); fmax2(accO[1], a01.y, wb2.y);
                    fmax2(accO[2], a23.x, wb2.y); fmax2(accO[3], a23.y, wb2.y);
                }
                if (more) commit(cb ^ 1);
                __syncthreads();
            }

            // epilogue
            float* hout = decH + ((long)cur * Ln + l) * BH;
            #pragma unroll
            for (int p = 0; p < 4; p++) {
                float2 vi = upk(accI[p]), vf = upk(accF[p]);
                float2 vg = upk(accG[p]), vo = upk(accO[p]);
                #pragma unroll
                for (int h2 = 0; h2 < 2; h2++) {
                    int r = m0 + mg8 + 2 * p + h2;
                    float gi = h2 ? vi.y : vi.x;
                    float gf = h2 ? vf.y : vf.x;
                    float gg = h2 ? vg.y : vg.x;
                    float go = h2 ? vo.y : vo.x;
                    float cc = creg[l][2 * p + h2];
                    float cn = sigf(gf) * cc + sigf(gi) * tanh_f(gg);
                    float hh = sigf(go) * tanh_f(cn);
                    creg[l][2 * p + h2] = cn;
                    hout[(long)r * Hn + j] = hh;
                }
            }
            mt_barrier(mt, &s_sense);
        }

        // ---- FC: rows of this mt, cols split over jb ----
        {
            const float* h3 = decH + ((long)cur * Ln + 3) * BH;
            float* oc = outbuf + (long)cur * Bn * INn;
            int i0 = jb * 6;
            int nc2 = INn - i0; if (nc2 > 6) nc2 = 6;
            for (int idx = tid; idx < 128 * nc2; idx += 256) {
                int r = idx / nc2, ii = idx - r * nc2;
                int i = i0 + ii;
                const float4* hr = (const float4*)(h3 + (long)(m0 + r) * Hn);
                const float4* wr = (const float4*)(fcW + (long)i * Hn);
                float acc = fcb[i];
                #pragma unroll
                for (int k = 0; k < 32; k++) {
                    float4 a = hr[k], b = wr[k];
                    acc = fmaf(a.x, b.x, acc); acc = fmaf(a.y, b.y, acc);
                    acc = fmaf(a.z, b.z, acc); acc = fmaf(a.w, b.w, acc);
                }
                int m = m0 + r;
                oc[(long)m * INn + i] = acc;
                dout[(long)m * Tn * INn + (long)t * INn + i] = acc;
            }
            mt_barrier(mt, &s_sense);
        }
    }
}

// ---------------------------------------------------------------------------
// Host orchestration: 16 pack nodes + 4 encoder + 1 decoder = 21 graph nodes.
// No memset/memcpy nodes; all state handled inside kernels.
// ---------------------------------------------------------------------------
extern "C" void kernel_launch(void* const* d_in, const int* in_sizes, int n_in,
                              void* d_out, int out_size)
{
    const float* x        = (const float*)d_in[0];
    const float* enc_Wih0 = (const float*)d_in[2];
    const float* enc_WihR = (const float*)d_in[3];
    const float* enc_Whh  = (const float*)d_in[4];
    const float* enc_b    = (const float*)d_in[5];
    const float* dec_Wih0 = (const float*)d_in[6];
    const float* dec_WihR = (const float*)d_in[7];
    const float* dec_Whh  = (const float*)d_in[8];
    const float* dec_b    = (const float*)d_in[9];
    const float* fc_W     = (const float*)d_in[10];
    const float* fc_b     = (const float*)d_in[11];
    float* out = (float*)d_out;

    float *ysA, *ysB, *encC, *decH, *outb, *wpk;
    cudaGetSymbolAddress((void**)&ysA,  g_ysA);
    cudaGetSymbolAddress((void**)&ysB,  g_ysB);
    cudaGetSymbolAddress((void**)&encC, g_encC);
    cudaGetSymbolAddress((void**)&decH, g_decH);
    cudaGetSymbolAddress((void**)&outb, g_out2);
    cudaGetSymbolAddress((void**)&wpk,  g_wpk);

    size_t smem0 = (size_t)(176 * 128 + 2 * 16 * PITCH) * 4;   // l0: 98.9 KB
    size_t smemR = (size_t)(256 * 128 + 2 * 16 * PITCH) * 4;   // l>=1: 147.9 KB
    cudaFuncSetAttribute(enc_layer_kernel,
                         cudaFuncAttributeMaxDynamicSharedMemorySize, (int)smemR);

    auto pack = [&](const float* W, long off, int K) {
        int total = 8 * K * 128;
        pack_w_kernel<<<(total + 255) / 256, 256>>>(W, wpk + off, K);
    };
    pack(enc_Wih0, OFF_EIH0, INn);
    for (int l = 1; l < Ln; l++) pack(enc_WihR + (long)(l - 1) * 512 * 128, OFF_EIHR + (l - 1) * PK_128, 128);
    for (int l = 0; l < Ln; l++) pack(enc_Whh  + (long)l * 512 * 128,       OFF_EHH  + l * PK_128,       128);
    pack(dec_Wih0, OFF_DIH0, INn);
    for (int l = 1; l < Ln; l++) pack(dec_WihR + (long)(l - 1) * 512 * 128, OFF_DIHR + (l - 1) * PK_128, 128);
    for (int l = 0; l < Ln; l++) pack(dec_Whh  + (long)l * 512 * 128,       OFF_DHH  + l * PK_128,       128);

    // ---- encoder: 4 persistent layer kernels ----
    enc_layer_kernel<<<128, 256, smem0>>>(
        x, (long)Sn * INn, (long)INn, INn, 48,
        wpk + OFF_EIH0, wpk + OFF_EHH, enc_b,
        ysA, decH + (long)(Ln + 0) * BH, encC);

    float* yin = ysA; float* yout = ysB;
    for (int l = 1; l < Ln; l++) {
        enc_layer_kernel<<<128, 256, smemR>>>(
            yin, (long)Hn, BH, 128, 128,
            wpk + OFF_EIHR + (long)(l - 1) * PK_128,
            wpk + OFF_EHH + (long)l * PK_128,
            enc_b + l * 512,
            yout, decH + (long)(Ln + l) * BH, encC + (long)l * BH);
        float* tmp = yin; yin = yout; yout = tmp;
    }

    // ---- decoder: one persistent kernel ----
    dec_kernel<<<128, 256>>>(x, wpk, dec_b, encC, decH, outb, fc_W, fc_b, out);
}